// round 6
// baseline (speedup 1.0000x reference)
#include <cuda_runtime.h>
#include <cuda_bf16.h>
#include <cstdint>

#define BB 2
#define HH 16
#define SS 2048
#define DD 64
#define BH (BB*HH)
#define SCALE 0.125f

static __device__ __align__(16) uint32_t g_mbits[(size_t)BB * SS * SS / 32];  // 1MB bit mask

// ---------------------------------------------------------------------------
// helpers
// ---------------------------------------------------------------------------
__device__ __forceinline__ uint32_t pk(float a, float b) {
    unsigned lo = (unsigned)__bfloat16_as_ushort(__float2bfloat16_rn(a));
    unsigned hi = (unsigned)__bfloat16_as_ushort(__float2bfloat16_rn(b));
    return lo | (hi << 16);
}
__device__ __forceinline__ void sp(float x, float& h, float& l) {
    __nv_bfloat16 hb = __float2bfloat16_rn(x);
    h = __bfloat162float(hb);
    l = x - h;
}

// mma.sync m16n8k16 row.col f32.bf16.bf16.f32 — D accumulates in place
#define MMA(d, a, b0v, b1v) \
    asm volatile("mma.sync.aligned.m16n8k16.row.col.f32.bf16.bf16.f32 " \
        "{%0,%1,%2,%3}, {%4,%5,%6,%7}, {%8,%9}, {%0,%1,%2,%3};" \
        : "+f"((d)[0]), "+f"((d)[1]), "+f"((d)[2]), "+f"((d)[3]) \
        : "r"((a)[0]), "r"((a)[1]), "r"((a)[2]), "r"((a)[3]), "r"(b0v), "r"(b1v))

// smem layout (bytes), phase-overlaid.
// Phase 1 K tiles: [key 128][d 64] bf16, row stride 144B. hi @0, lo @18432.
// Phase 2 V tiles (transposed): [d 64][key 128] bf16, row stride 272B. hi @0, lo @17408.
#define SM_KH 0
#define SM_KL 18432
#define SM_VH 0
#define SM_VL 17408
#define SMEM_BYTES 36864

// ---------------------------------------------------------------------------
// Kernel 0: bit-pack the int32 mask. word w covers elements [w*32, w*32+32)
// ---------------------------------------------------------------------------
__global__ __launch_bounds__(256)
void mask_pack(const int* __restrict__ mask)
{
    const size_t w = (size_t)blockIdx.x * 256 + threadIdx.x;   // 262144 words
    const int4* p = (const int4*)mask + w * 8;
    uint32_t bits = 0;
    #pragma unroll
    for (int j = 0; j < 8; j++) {
        int4 x = p[j];
        bits |= (x.x ? 1u : 0u) << (j * 4 + 0);
        bits |= (x.y ? 1u : 0u) << (j * 4 + 1);
        bits |= (x.z ? 1u : 0u) << (j * 4 + 2);
        bits |= (x.w ? 1u : 0u) << (j * 4 + 3);
    }
    g_mbits[w] = bits;
}

// ---------------------------------------------------------------------------
// device routines (R4-proven forms)
// ---------------------------------------------------------------------------
__device__ __forceinline__ void load_q_frags(const float* __restrict__ q,
                                             int bh, int r0, int r8, int t,
                                             uint32_t (&qh)[4][4], uint32_t (&ql)[4][4])
{
    const float* qp = q + (size_t)bh * SS * DD;
    #pragma unroll
    for (int ks = 0; ks < 4; ks++) {
        const int c = ks * 16 + t * 2;
        float2 x0 = *(const float2*)(qp + (size_t)r0 * DD + c);
        float2 x1 = *(const float2*)(qp + (size_t)r8 * DD + c);
        float2 x2 = *(const float2*)(qp + (size_t)r0 * DD + c + 8);
        float2 x3 = *(const float2*)(qp + (size_t)r8 * DD + c + 8);
        float h0,l0,h1,l1;
        sp(x0.x*SCALE,h0,l0); sp(x0.y*SCALE,h1,l1);
        qh[ks][0]=pk(h0,h1); ql[ks][0]=pk(l0,l1);
        sp(x1.x*SCALE,h0,l0); sp(x1.y*SCALE,h1,l1);
        qh[ks][1]=pk(h0,h1); ql[ks][1]=pk(l0,l1);
        sp(x2.x*SCALE,h0,l0); sp(x2.y*SCALE,h1,l1);
        qh[ks][2]=pk(h0,h1); ql[ks][2]=pk(l0,l1);
        sp(x3.x*SCALE,h0,l0); sp(x3.y*SCALE,h1,l1);
        qh[ks][3]=pk(h0,h1); ql[ks][3]=pk(l0,l1);
    }
}

__device__ __forceinline__ void stage_k_tile(char* smem, const float* __restrict__ k,
                                             int bh, int n0, int tid)
{
    const int r  = tid >> 1;
    const int c0 = (tid & 1) * 32;
    const float* kp = k + ((size_t)bh * SS + n0 + r) * DD + c0;
    #pragma unroll
    for (int i = 0; i < 8; i++) {
        float4 f = *(const float4*)(kp + i * 4);
        float hx,lx,hy,ly,hz,lz,hw,lw;
        sp(f.x,hx,lx); sp(f.y,hy,ly); sp(f.z,hz,lz); sp(f.w,hw,lw);
        const int off = r * 144 + (c0 + i * 4) * 2;
        *(uint2*)(smem + SM_KH + off) = make_uint2(pk(hx,hy), pk(hz,hw));
        *(uint2*)(smem + SM_KL + off) = make_uint2(pk(lx,ly), pk(lz,lw));
    }
}

// QK^T for one 128-key tile: s[nt][4] += bf16x3(Q * K^T)  (scalar-LDS form)
__device__ __forceinline__ void qk_tile(const char* smem, int g, int t,
                                        const uint32_t (&qh)[4][4],
                                        const uint32_t (&ql)[4][4],
                                        float (&s)[16][4])
{
    #pragma unroll
    for (int ks = 0; ks < 4; ks++) {
        #pragma unroll
        for (int pass = 0; pass < 3; pass++) {
            const uint32_t* A = (pass == 2) ? ql[ks] : qh[ks];
            const int bb = (pass == 1) ? SM_KL : SM_KH;
            #pragma unroll
            for (int nt = 0; nt < 16; nt++) {
                const char* ad = smem + bb + (nt * 8 + g) * 144 + ks * 32 + t * 4;
                uint32_t b0 = *(const uint32_t*)ad;
                uint32_t b1 = *(const uint32_t*)(ad + 16);
                MMA(s[nt], A, b0, b1);
            }
        }
    }
}

// ---------------------------------------------------------------------------
// Fused kernel: phase 1 QK -> e=exp(masked score) stored in atten + rowsums;
//               phase 2 read e, p=e/sum, rewrite atten, AV, write out.
// ---------------------------------------------------------------------------
__global__ void __launch_bounds__(256)
sdpa_fused(const float* __restrict__ q, const float* __restrict__ k,
           const float* __restrict__ v,
           float* __restrict__ atten, float* __restrict__ out)
{
    extern __shared__ char smem[];
    const int tid  = threadIdx.x;
    const int w    = tid >> 5;
    const int lane = tid & 31;
    const int g    = lane >> 2;
    const int t    = lane & 3;
    const int bh   = blockIdx.y;
    const int b    = bh / HH;
    const int q0   = blockIdx.x * 128;
    const int r0   = q0 + w * 16 + g;
    const int r8   = r0 + 8;

    const size_t mb0 = ((size_t)b * SS + r0) * 64;
    const size_t mb8 = ((size_t)b * SS + r8) * 64;
    float* arow_g  = atten + ((size_t)bh * SS + r0) * SS;
    float* arow_g8 = atten + ((size_t)bh * SS + r8) * SS;

    // ---------------- phase 1: QK, e = exp or 0, rowsums ----------------
    uint32_t qh[4][4], ql[4][4];
    load_q_frags(q, bh, r0, r8, t, qh, ql);

    float sum_g = 0.0f, sum_g8 = 0.0f;

    for (int kt = 0; kt < 16; kt++) {
        const int n0 = kt * 128;
        __syncthreads();
        stage_k_tile(smem, k, bh, n0, tid);
        __syncthreads();

        float s[16][4];
        #pragma unroll
        for (int nt = 0; nt < 16; nt++)
            #pragma unroll
            for (int i = 0; i < 4; i++) s[nt][i] = 0.0f;

        qk_tile(smem, g, t, qh, ql, s);

        uint4 mg = *(const uint4*)(g_mbits + mb0 + n0 / 32);
        uint4 m8 = *(const uint4*)(g_mbits + mb8 + n0 / 32);
        const uint32_t* mgw = (const uint32_t*)&mg;
        const uint32_t* m8w = (const uint32_t*)&m8;
        #pragma unroll
        for (int nt = 0; nt < 16; nt++) {
            const uint32_t wg = mgw[nt >> 2] >> ((nt & 3) * 8 + t * 2);
            const uint32_t w8 = m8w[nt >> 2] >> ((nt & 3) * 8 + t * 2);
            const float e0 = (wg      & 1) ? 0.0f : __expf(s[nt][0]);
            const float e1 = (wg >> 1 & 1) ? 0.0f : __expf(s[nt][1]);
            const float e2 = (w8      & 1) ? 0.0f : __expf(s[nt][2]);
            const float e3 = (w8 >> 1 & 1) ? 0.0f : __expf(s[nt][3]);
            sum_g  += e0 + e1;
            sum_g8 += e2 + e3;
            const int c = n0 + nt * 8 + t * 2;
            *(float2*)(arow_g  + c) = make_float2(e0, e1);
            *(float2*)(arow_g8 + c) = make_float2(e2, e3);
        }
    }

    sum_g  += __shfl_xor_sync(0xffffffffu, sum_g, 1);
    sum_g  += __shfl_xor_sync(0xffffffffu, sum_g, 2);
    sum_g8 += __shfl_xor_sync(0xffffffffu, sum_g8, 1);
    sum_g8 += __shfl_xor_sync(0xffffffffu, sum_g8, 2);
    const float inv_g  = 1.0f / sum_g;
    const float inv_g8 = 1.0f / sum_g8;

    // ---------------- phase 2: p = e*inv, AV ----------------
    float o[8][4];
    #pragma unroll
    for (int nd = 0; nd < 8; nd++)
        #pragma unroll
        for (int i = 0; i < 4; i++) o[nd][i] = 0.0f;

    for (int kt = 0; kt < 16; kt++) {
        const int n0 = kt * 128;
        __syncthreads();   // previous phase/iteration readers done before overwrite
        // stage V transposed: Vt[d][key] hi/lo, row stride 272B
        {
            const int kp2 = tid >> 2;            // key pair 0..63
            const int c0v = (tid & 3) * 16;      // d range
            const float* vp = v + ((size_t)bh * SS + n0 + 2 * kp2) * DD + c0v;
            #pragma unroll
            for (int i = 0; i < 4; i++) {
                float4 a0 = *(const float4*)(vp + i * 4);
                float4 a1 = *(const float4*)(vp + DD + i * 4);
                const float e0[4] = {a0.x, a0.y, a0.z, a0.w};
                const float e1[4] = {a1.x, a1.y, a1.z, a1.w};
                #pragma unroll
                for (int j = 0; j < 4; j++) {
                    const int d = c0v + i * 4 + j;
                    float h0,l0,h1,l1;
                    sp(e0[j], h0, l0);
                    sp(e1[j], h1, l1);
                    *(uint32_t*)(smem + SM_VH + d * 272 + kp2 * 4) = pk(h0, h1);
                    *(uint32_t*)(smem + SM_VL + d * 272 + kp2 * 4) = pk(l0, l1);
                }
            }
        }
        __syncthreads();

        #pragma unroll
        for (int kap = 0; kap < 8; kap++) {
            uint32_t ah[4], al[4];
            #pragma unroll
            for (int i = 0; i < 2; i++) {
                const int nt = kap * 2 + i;
                const int c = n0 + nt * 8 + t * 2;
                float2 eg = *(const float2*)(arow_g  + c);
                float2 e8 = *(const float2*)(arow_g8 + c);
                const float p0 = eg.x * inv_g;
                const float p1 = eg.y * inv_g;
                const float p2 = e8.x * inv_g8;
                const float p3 = e8.y * inv_g8;
                *(float2*)(arow_g  + c) = make_float2(p0, p1);
                *(float2*)(arow_g8 + c) = make_float2(p2, p3);
                float h0,l0,h1,l1,h2,l2,h3,l3;
                sp(p0,h0,l0); sp(p1,h1,l1); sp(p2,h2,l2); sp(p3,h3,l3);
                ah[i*2+0] = pk(h0,h1); al[i*2+0] = pk(l0,l1);
                ah[i*2+1] = pk(h2,h3); al[i*2+1] = pk(l2,l3);
            }
            #pragma unroll
            for (int nd = 0; nd < 8; nd++) {
                const char* vh = smem + SM_VH + (nd * 8 + g) * 272 + kap * 32 + t * 4;
                const char* vl = smem + SM_VL + (nd * 8 + g) * 272 + kap * 32 + t * 4;
                uint32_t bh0 = *(const uint32_t*)vh;
                uint32_t bh1 = *(const uint32_t*)(vh + 16);
                uint32_t bl0 = *(const uint32_t*)vl;
                uint32_t bl1 = *(const uint32_t*)(vl + 16);
                MMA(o[nd], ah, bh0, bh1);
                MMA(o[nd], ah, bl0, bl1);
                MMA(o[nd], al, bh0, bh1);
            }
        }
    }

    float* orow_g  = out + ((size_t)bh * SS + r0) * DD;
    float* orow_g8 = out + ((size_t)bh * SS + r8) * DD;
    #pragma unroll
    for (int nd = 0; nd < 8; nd++) {
        *(float2*)(orow_g  + nd * 8 + t * 2) = make_float2(o[nd][0], o[nd][1]);
        *(float2*)(orow_g8 + nd * 8 + t * 2) = make_float2(o[nd][2], o[nd][3]);
    }
}

// ---------------------------------------------------------------------------
extern "C" void kernel_launch(void* const* d_in, const int* in_sizes, int n_in,
                              void* d_out, int out_size)
{
    const float* q = (const float*)d_in[0];
    const float* k = (const float*)d_in[1];
    const float* v = (const float*)d_in[2];
    const int*   mask = (const int*)d_in[3];

    float* out   = (float*)d_out;                 // [B,H,S,D]
    float* atten = out + (size_t)BH * SS * DD;    // [B,H,S,S]

    cudaFuncSetAttribute(sdpa_fused, cudaFuncAttributeMaxDynamicSharedMemorySize, SMEM_BYTES);

    dim3 grid(SS / 128, BH);
    mask_pack<<<1024, 256>>>(mask);
    sdpa_fused<<<grid, 256, SMEM_BYTES>>>(q, k, v, atten, out);
    (void)in_sizes; (void)n_in; (void)out_size;
}

// round 7
// speedup vs baseline: 2.0458x; 2.0458x over previous
#include <cuda_runtime.h>
#include <cuda_bf16.h>
#include <cstdint>

#define BB 2
#define HH 16
#define SS 2048
#define DD 64
#define BH (BB*HH)
#define SCALE 0.125f

static __device__ float g_row_s[BH * SS];
static __device__ __align__(16) uint32_t g_mbits[(size_t)BB * SS * SS / 32];  // 1MB bit mask

// ---------------------------------------------------------------------------
// helpers
// ---------------------------------------------------------------------------
__device__ __forceinline__ uint32_t pk(float a, float b) {
    unsigned lo = (unsigned)__bfloat16_as_ushort(__float2bfloat16_rn(a));
    unsigned hi = (unsigned)__bfloat16_as_ushort(__float2bfloat16_rn(b));
    return lo | (hi << 16);
}
__device__ __forceinline__ void sp(float x, float& h, float& l) {
    __nv_bfloat16 hb = __float2bfloat16_rn(x);
    h = __bfloat162float(hb);
    l = x - h;
}

// mma.sync m16n8k16 row.col f32.bf16.bf16.f32 — D accumulates in place
#define MMA(d, a, b0v, b1v) \
    asm volatile("mma.sync.aligned.m16n8k16.row.col.f32.bf16.bf16.f32 " \
        "{%0,%1,%2,%3}, {%4,%5,%6,%7}, {%8,%9}, {%0,%1,%2,%3};" \
        : "+f"((d)[0]), "+f"((d)[1]), "+f"((d)[2]), "+f"((d)[3]) \
        : "r"((a)[0]), "r"((a)[1]), "r"((a)[2]), "r"((a)[3]), "r"(b0v), "r"(b1v))

// smem layout (bytes).
// K tiles: [key 128][d 64] bf16, row stride 144B. hi/lo.
// V tiles (transposed): [d 64][key 128] bf16, row stride 272B. hi/lo.
#define SM_KH 0
#define SM_KL 18432
#define SM_VH 36864
#define SM_VL 54272
#define SMEM_BYTES 71680

// ---------------------------------------------------------------------------
// Kernel 0: bit-pack the int32 mask. word w covers elements [w*32, w*32+32)
// ---------------------------------------------------------------------------
__global__ __launch_bounds__(256)
void mask_pack(const int* __restrict__ mask)
{
    const size_t w = (size_t)blockIdx.x * 256 + threadIdx.x;   // 262144 words
    const int4* p = (const int4*)mask + w * 8;
    uint32_t bits = 0;
    #pragma unroll
    for (int j = 0; j < 8; j++) {
        int4 x = p[j];
        bits |= (x.x ? 1u : 0u) << (j * 4 + 0);
        bits |= (x.y ? 1u : 0u) << (j * 4 + 1);
        bits |= (x.z ? 1u : 0u) << (j * 4 + 2);
        bits |= (x.w ? 1u : 0u) << (j * 4 + 3);
    }
    g_mbits[w] = bits;
}

// ---------------------------------------------------------------------------
// device routines (R4-proven forms)
// ---------------------------------------------------------------------------
__device__ __forceinline__ void load_q_frags(const float* __restrict__ q,
                                             int bh, int r0, int r8, int t,
                                             uint32_t (&qh)[4][4], uint32_t (&ql)[4][4])
{
    const float* qp = q + (size_t)bh * SS * DD;
    #pragma unroll
    for (int ks = 0; ks < 4; ks++) {
        const int c = ks * 16 + t * 2;
        float2 x0 = *(const float2*)(qp + (size_t)r0 * DD + c);
        float2 x1 = *(const float2*)(qp + (size_t)r8 * DD + c);
        float2 x2 = *(const float2*)(qp + (size_t)r0 * DD + c + 8);
        float2 x3 = *(const float2*)(qp + (size_t)r8 * DD + c + 8);
        float h0,l0,h1,l1;
        sp(x0.x*SCALE,h0,l0); sp(x0.y*SCALE,h1,l1);
        qh[ks][0]=pk(h0,h1); ql[ks][0]=pk(l0,l1);
        sp(x1.x*SCALE,h0,l0); sp(x1.y*SCALE,h1,l1);
        qh[ks][1]=pk(h0,h1); ql[ks][1]=pk(l0,l1);
        sp(x2.x*SCALE,h0,l0); sp(x2.y*SCALE,h1,l1);
        qh[ks][2]=pk(h0,h1); ql[ks][2]=pk(l0,l1);
        sp(x3.x*SCALE,h0,l0); sp(x3.y*SCALE,h1,l1);
        qh[ks][3]=pk(h0,h1); ql[ks][3]=pk(l0,l1);
    }
}

__device__ __forceinline__ void stage_k_tile(char* smem, const float* __restrict__ k,
                                             int bh, int n0, int tid)
{
    const int r  = tid >> 1;
    const int c0 = (tid & 1) * 32;
    const float* kp = k + ((size_t)bh * SS + n0 + r) * DD + c0;
    #pragma unroll
    for (int i = 0; i < 8; i++) {
        float4 f = *(const float4*)(kp + i * 4);
        float hx,lx,hy,ly,hz,lz,hw,lw;
        sp(f.x,hx,lx); sp(f.y,hy,ly); sp(f.z,hz,lz); sp(f.w,hw,lw);
        const int off = r * 144 + (c0 + i * 4) * 2;
        *(uint2*)(smem + SM_KH + off) = make_uint2(pk(hx,hy), pk(hz,hw));
        *(uint2*)(smem + SM_KL + off) = make_uint2(pk(lx,ly), pk(lz,lw));
    }
}

__device__ __forceinline__ void stage_v_tile(char* smem, const float* __restrict__ v,
                                             int bh, int n0, int tid)
{
    const int kp2 = tid >> 2;            // key pair 0..63
    const int c0v = (tid & 3) * 16;      // d range
    const float* vp = v + ((size_t)bh * SS + n0 + 2 * kp2) * DD + c0v;
    #pragma unroll
    for (int i = 0; i < 4; i++) {
        float4 a0 = *(const float4*)(vp + i * 4);
        float4 a1 = *(const float4*)(vp + DD + i * 4);
        const float e0[4] = {a0.x, a0.y, a0.z, a0.w};
        const float e1[4] = {a1.x, a1.y, a1.z, a1.w};
        #pragma unroll
        for (int j = 0; j < 4; j++) {
            const int d = c0v + i * 4 + j;
            float h0,l0,h1,l1;
            sp(e0[j], h0, l0);
            sp(e1[j], h1, l1);
            *(uint32_t*)(smem + SM_VH + d * 272 + kp2 * 4) = pk(h0, h1);
            *(uint32_t*)(smem + SM_VL + d * 272 + kp2 * 4) = pk(l0, l1);
        }
    }
}

// ---------------------------------------------------------------------------
// Kernel 1: flash pass. e = exp(masked score) -> atten (unnormalized),
//           O = sum e*V, out = O/sum, g_row_s = sum.
// ---------------------------------------------------------------------------
__global__ void __launch_bounds__(256, 2)
sdpa_flash(const float* __restrict__ q, const float* __restrict__ k,
           const float* __restrict__ v,
           float* __restrict__ atten, float* __restrict__ out)
{
    extern __shared__ char smem[];
    const int tid  = threadIdx.x;
    const int w    = tid >> 5;
    const int lane = tid & 31;
    const int g    = lane >> 2;
    const int t    = lane & 3;
    const int bh   = blockIdx.y;
    const int b    = bh / HH;
    const int q0   = blockIdx.x * 128;
    const int r0   = q0 + w * 16 + g;
    const int r8   = r0 + 8;

    const size_t mb0 = ((size_t)b * SS + r0) * 64;
    const size_t mb8 = ((size_t)b * SS + r8) * 64;
    float* arow_g  = atten + ((size_t)bh * SS + r0) * SS;
    float* arow_g8 = atten + ((size_t)bh * SS + r8) * SS;

    uint32_t qh[4][4], ql[4][4];
    load_q_frags(q, bh, r0, r8, t, qh, ql);

    float sum_g = 0.0f, sum_g8 = 0.0f;
    float o[8][4];
    #pragma unroll
    for (int nd = 0; nd < 8; nd++)
        #pragma unroll
        for (int i = 0; i < 4; i++) o[nd][i] = 0.0f;

    for (int kt = 0; kt < 16; kt++) {
        const int n0 = kt * 128;
        __syncthreads();
        stage_k_tile(smem, k, bh, n0, tid);
        stage_v_tile(smem, v, bh, n0, tid);
        __syncthreads();

        uint4 mg = *(const uint4*)(g_mbits + mb0 + n0 / 32);
        uint4 m8 = *(const uint4*)(g_mbits + mb8 + n0 / 32);
        const uint32_t* mgw = (const uint32_t*)&mg;
        const uint32_t* m8w = (const uint32_t*)&m8;

        // process the 128-key tile in two 64-key halves (register economy)
        #pragma unroll
        for (int h = 0; h < 2; h++) {
            float s[8][4];
            #pragma unroll
            for (int nt = 0; nt < 8; nt++)
                #pragma unroll
                for (int i = 0; i < 4; i++) s[nt][i] = 0.0f;

            // QK for this half
            #pragma unroll
            for (int ks = 0; ks < 4; ks++) {
                #pragma unroll
                for (int pass = 0; pass < 3; pass++) {
                    const uint32_t* A = (pass == 2) ? ql[ks] : qh[ks];
                    const int bb = (pass == 1) ? SM_KL : SM_KH;
                    #pragma unroll
                    for (int nt = 0; nt < 8; nt++) {
                        const char* ad = smem + bb + ((h * 8 + nt) * 8 + g) * 144 + ks * 32 + t * 4;
                        uint32_t b0 = *(const uint32_t*)ad;
                        uint32_t b1 = *(const uint32_t*)(ad + 16);
                        MMA(s[nt], A, b0, b1);
                    }
                }
            }

            // epilogue + AV for this half
            #pragma unroll
            for (int kap = 0; kap < 4; kap++) {
                uint32_t ah[4], al[4];
                #pragma unroll
                for (int i = 0; i < 2; i++) {
                    const int nt  = kap * 2 + i;       // within half
                    const int ntg = h * 8 + nt;        // within 128-key tile
                    const uint32_t wg = mgw[ntg >> 2] >> ((ntg & 3) * 8 + t * 2);
                    const uint32_t w8 = m8w[ntg >> 2] >> ((ntg & 3) * 8 + t * 2);
                    const float e0 = (wg      & 1) ? 0.0f : __expf(s[nt][0]);
                    const float e1 = (wg >> 1 & 1) ? 0.0f : __expf(s[nt][1]);
                    const float e2 = (w8      & 1) ? 0.0f : __expf(s[nt][2]);
                    const float e3 = (w8 >> 1 & 1) ? 0.0f : __expf(s[nt][3]);
                    sum_g  += e0 + e1;
                    sum_g8 += e2 + e3;
                    const int c = n0 + ntg * 8 + t * 2;
                    *(float2*)(arow_g  + c) = make_float2(e0, e1);
                    *(float2*)(arow_g8 + c) = make_float2(e2, e3);
                    float h0,l0,h1,l1,h2,l2,h3,l3;
                    sp(e0,h0,l0); sp(e1,h1,l1); sp(e2,h2,l2); sp(e3,h3,l3);
                    ah[i*2+0] = pk(h0,h1); al[i*2+0] = pk(l0,l1);
                    ah[i*2+1] = pk(h2,h3); al[i*2+1] = pk(l2,l3);
                }
                #pragma unroll
                for (int nd = 0; nd < 8; nd++) {
                    const int vbase = (nd * 8 + g) * 272 + (h * 4 + kap) * 32 + t * 4;
                    const char* vh = smem + SM_VH + vbase;
                    const char* vl = smem + SM_VL + vbase;
                    uint32_t bh0 = *(const uint32_t*)vh;
                    uint32_t bh1 = *(const uint32_t*)(vh + 16);
                    uint32_t bl0 = *(const uint32_t*)vl;
                    uint32_t bl1 = *(const uint32_t*)(vl + 16);
                    MMA(o[nd], ah, bh0, bh1);
                    MMA(o[nd], ah, bl0, bl1);
                    MMA(o[nd], al, bh0, bh1);
                }
            }
        }
    }

    // reduce row sums across the 4 t-lanes
    sum_g  += __shfl_xor_sync(0xffffffffu, sum_g, 1);
    sum_g  += __shfl_xor_sync(0xffffffffu, sum_g, 2);
    sum_g8 += __shfl_xor_sync(0xffffffffu, sum_g8, 1);
    sum_g8 += __shfl_xor_sync(0xffffffffu, sum_g8, 2);
    const float inv_g  = 1.0f / sum_g;
    const float inv_g8 = 1.0f / sum_g8;
    if (t == 0) {
        g_row_s[bh * SS + r0] = sum_g;
        g_row_s[bh * SS + r8] = sum_g8;
    }

    float* orow_g  = out + ((size_t)bh * SS + r0) * DD;
    float* orow_g8 = out + ((size_t)bh * SS + r8) * DD;
    #pragma unroll
    for (int nd = 0; nd < 8; nd++) {
        *(float2*)(orow_g  + nd * 8 + t * 2) = make_float2(o[nd][0] * inv_g,  o[nd][1] * inv_g);
        *(float2*)(orow_g8 + nd * 8 + t * 2) = make_float2(o[nd][2] * inv_g8, o[nd][3] * inv_g8);
    }
}

// ---------------------------------------------------------------------------
// Kernel 2: atten[row, :] *= 1/g_row_s[row]. One block per row, streaming.
// ---------------------------------------------------------------------------
__global__ void __launch_bounds__(256)
atten_norm(float* __restrict__ atten)
{
    const int row = blockIdx.x;                 // 0 .. BH*SS-1
    const float inv = 1.0f / g_row_s[row];
    float4* p = (float4*)(atten + (size_t)row * SS);
    const int i0 = threadIdx.x;
    float4 a = p[i0];
    float4 c = p[i0 + 256];
    a.x *= inv; a.y *= inv; a.z *= inv; a.w *= inv;
    c.x *= inv; c.y *= inv; c.z *= inv; c.w *= inv;
    p[i0] = a;
    p[i0 + 256] = c;
}

// ---------------------------------------------------------------------------
extern "C" void kernel_launch(void* const* d_in, const int* in_sizes, int n_in,
                              void* d_out, int out_size)
{
    const float* q = (const float*)d_in[0];
    const float* k = (const float*)d_in[1];
    const float* v = (const float*)d_in[2];
    const int*   mask = (const int*)d_in[3];

    float* out   = (float*)d_out;                 // [B,H,S,D]
    float* atten = out + (size_t)BH * SS * DD;    // [B,H,S,S]

    cudaFuncSetAttribute(sdpa_flash, cudaFuncAttributeMaxDynamicSharedMemorySize, SMEM_BYTES);

    dim3 grid(SS / 128, BH);
    mask_pack<<<1024, 256>>>(mask);
    sdpa_flash<<<grid, 256, SMEM_BYTES>>>(q, k, v, atten, out);
    atten_norm<<<BH * SS, 256>>>(atten);
    (void)in_sizes; (void)n_in; (void)out_size;
}